// round 12
// baseline (speedup 1.0000x reference)
#include <cuda_runtime.h>
#include <cuda_bf16.h>
#include <stdint.h>
#include <math.h>

// Problem constants
#define BATCH 16
#define C_IN  256
#define W_DIM 64
#define HW    4096     // 64*64
#define HWP   1024     // pooled 32*32
#define CK    32       // f/g channels
#define CH    128      // h channels
#define OC_TOT 192

// Scratch (static device globals). tf32 bit patterns everywhere.
__device__ uint32_t d_f[(size_t)BATCH * CK * HW];
__device__ uint32_t d_gbuf[(size_t)BATCH * CK * HWP];
__device__ uint32_t d_hbuf[(size_t)BATCH * CH * HWP];
__device__ uint32_t d_wcat[OC_TOT * C_IN];             // [oc][256] tf32 (f,g,h weights)
__device__ uint32_t d_wvt[C_IN * CH];                  // [oc][128] tf32 (wv)

// ---------------------------------------------------------------------------
// helpers
// ---------------------------------------------------------------------------
__device__ __forceinline__ uint32_t f2tf(float x) {
    uint32_t r;
    asm("cvt.rna.tf32.f32 %0, %1;" : "=r"(r) : "f"(x));
    return r;
}
__device__ __forceinline__ uint32_t f2tf_u(uint32_t xb) {
    uint32_t r;
    asm("cvt.rna.tf32.f32 %0, %1;" : "=r"(r) : "r"(xb));
    return r;
}

__device__ __forceinline__ void mma8(float* d, const uint32_t* a, const uint32_t* b) {
    asm volatile(
        "mma.sync.aligned.m16n8k8.row.col.f32.tf32.tf32.f32 "
        "{%0,%1,%2,%3},{%4,%5,%6,%7},{%8,%9},{%0,%1,%2,%3};\n"
        : "+f"(d[0]), "+f"(d[1]), "+f"(d[2]), "+f"(d[3])
        : "r"(a[0]), "r"(a[1]), "r"(a[2]), "r"(a[3]), "r"(b[0]), "r"(b[1]));
}

__device__ __forceinline__ uint32_t s2u(const void* p) {
    return (uint32_t)__cvta_generic_to_shared(p);
}

__device__ __forceinline__ void cp16(void* dst, const void* src) {
    asm volatile("cp.async.cg.shared.global [%0], [%1], 16;\n"
                 :: "r"(s2u(dst)), "l"(src));
}
__device__ __forceinline__ void cp4(void* dst, const void* src) {
    asm volatile("cp.async.ca.shared.global [%0], [%1], 4;\n"
                 :: "r"(s2u(dst)), "l"(src));
}
__device__ __forceinline__ void cp_commit() {
    asm volatile("cp.async.commit_group;\n" ::);
}
__device__ __forceinline__ void cp_wait_all() {
    asm volatile("cp.async.wait_group 0;\n" ::);
}

// A fragment (m16 x k8 tf32), smem layout [m][k], rs words/row
__device__ __forceinline__ void ldsmA(uint32_t* r, const uint32_t* base, int rs,
                                      int m_base, int k_base, int lane) {
    const uint32_t* p = base + (size_t)(m_base + (lane & 15)) * rs + k_base + ((lane >> 4) << 2);
    uint32_t addr = s2u(p);
    asm volatile("ldmatrix.sync.aligned.m8n8.x4.shared.b16 {%0,%1,%2,%3},[%4];"
                 : "=r"(r[0]), "=r"(r[1]), "=r"(r[2]), "=r"(r[3]) : "r"(addr));
}

// B fragments for two n8 tiles (k8), smem layout [n][k]
__device__ __forceinline__ void ldsmB(uint32_t* r, const uint32_t* base, int rs,
                                      int n_base, int k_base, int lane) {
    int row = n_base + (lane & 7) + (((lane >> 4) & 1) << 3);
    int col = k_base + (((lane >> 3) & 1) << 2);
    const uint32_t* p = base + (size_t)row * rs + col;
    uint32_t addr = s2u(p);
    asm volatile("ldmatrix.sync.aligned.m8n8.x4.shared.b16 {%0,%1,%2,%3},[%4];"
                 : "=r"(r[0]), "=r"(r[1]), "=r"(r[2]), "=r"(r[3]) : "r"(addr));
}

#define RS36 36    // pitch (words), 144B = 16 mod 128 -> LDSM conflict-free
#define PS   132   // pitch for 128-wide k tiles (528B = 16 mod 128)
#define HP68 68    // pitch for 64-wide k tiles (272B = 16 mod 128, cp16-aligned)

// ---------------------------------------------------------------------------
// Kernel 0: pre-convert weights to tf32
// ---------------------------------------------------------------------------
__global__ __launch_bounds__(256)
void prep_weights(const float* __restrict__ wf, const float* __restrict__ wg,
                  const float* __restrict__ wh, const float* __restrict__ wv)
{
    int i = blockIdx.x * 256 + threadIdx.x;
    if (i < OC_TOT * C_IN) {
        int oc = i >> 8, k = i & 255;
        float v;
        if (oc < 32)       v = wf[oc * C_IN + k];
        else if (oc < 64)  v = wg[(oc - 32) * C_IN + k];
        else               v = wh[(oc - 64) * C_IN + k];
        d_wcat[i] = f2tf(v);
    }
    int j = i - OC_TOT * C_IN;
    if (j >= 0 && j < C_IN * CH) d_wvt[j] = f2tf(wv[j]);
}

// ---------------------------------------------------------------------------
// Kernel 1: projection GEMM + bias + (g/h) fused 2x2 maxpool. (unchanged)
// ---------------------------------------------------------------------------
__global__ __launch_bounds__(256)
void proj_gemm(const float* __restrict__ x,
               const float* __restrict__ bf, const float* __restrict__ bg,
               const float* __restrict__ bh)
{
    extern __shared__ uint32_t smp[];
    uint32_t* As = smp;                       // 2 x [64 m][RS36]
    uint32_t* Bs = As + 2 * 64 * RS36;        // 2 x [128 n][RS36]

    const int b  = blockIdx.z;
    const int n0 = blockIdx.x * 128;
    const int m0 = blockIdx.y * 64;
    const float* xb = x + (size_t)b * C_IN * HW;

    const int t = threadIdx.x, lane = t & 31, wid = t >> 5;
    const int wm = wid & 1, wn = wid >> 1;

    auto issue_chunk = [&](int k0, int buf) {
        uint32_t* ad = As + buf * 64 * RS36;
        uint32_t* bd = Bs + buf * 128 * RS36;
        #pragma unroll
        for (int ii = 0; ii < 2; ii++) {
            int i = t + ii * 256;                 // < 512
            int m = i >> 3, k4 = (i & 7) * 4;
            cp16(&ad[m * RS36 + k4], d_wcat + (size_t)(m0 + m) * C_IN + k0 + k4);
        }
        #pragma unroll
        for (int ii = 0; ii < 4; ii++) {
            int i = t + ii * 256;                 // < 1024
            int n  = (i & 31) + ((i >> 5) & 3) * 32;
            int k4 = (i >> 7) * 4;
            #pragma unroll
            for (int j = 0; j < 4; j++)
                cp4(&bd[n * RS36 + k4 + j], xb + (size_t)(k0 + k4 + j) * HW + n0 + n);
        }
        cp_commit();
    };

    issue_chunk(0, 0);

    float acc[2][4][4] = {};

    for (int ic = 0; ic < 8; ic++) {
        cp_wait_all();
        __syncthreads();
        if (ic + 1 < 8) issue_chunk((ic + 1) * 32, (ic + 1) & 1);

        const uint32_t* abuf = As + (ic & 1) * 64 * RS36;
        const uint32_t* bbuf = Bs + (ic & 1) * 128 * RS36;

        #pragma unroll
        for (int kk = 0; kk < 4; kk++) {
            uint32_t a0[4], a1[4], b01[4], b23[4];
            ldsmA(a0, abuf, RS36, wm * 32,      kk * 8, lane);
            ldsmA(a1, abuf, RS36, wm * 32 + 16, kk * 8, lane);
            ldsmB(b01, bbuf, RS36, wn * 32,      kk * 8, lane);
            ldsmB(b23, bbuf, RS36, wn * 32 + 16, kk * 8, lane);
            #pragma unroll
            for (int j = 0; j < 4; j++) { b01[j] = f2tf_u(b01[j]); b23[j] = f2tf_u(b23[j]); }
            mma8(acc[0][0], a0, b01); mma8(acc[0][1], a0, b01 + 2);
            mma8(acc[0][2], a0, b23); mma8(acc[0][3], a0, b23 + 2);
            mma8(acc[1][0], a1, b01); mma8(acc[1][1], a1, b01 + 2);
            mma8(acc[1][2], a1, b23); mma8(acc[1][3], a1, b23 + 2);
        }
    }
    __syncthreads();

    float* psm = reinterpret_cast<float*>(As);

    #pragma unroll
    for (int mt = 0; mt < 2; mt++) {
        #pragma unroll
        for (int dr = 0; dr < 2; dr++) {
            int ocl = wm * 32 + mt * 16 + dr * 8 + (lane >> 2);
            int oc = m0 + ocl;
            #pragma unroll
            for (int nt = 0; nt < 4; nt++) {
                int nloc = wn * 32 + nt * 8 + 2 * (lane & 3);
                float v0 = acc[mt][nt][dr * 2 + 0];
                float v1 = acc[mt][nt][dr * 2 + 1];
                if (oc < 32) {
                    float bias = bf[oc];
                    *reinterpret_cast<uint2*>(
                        d_f + ((size_t)b * CK + oc) * HW + n0 + nloc) =
                        make_uint2(f2tf(v0 + bias), f2tf(v1 + bias));
                } else {
                    int pr = nloc >> 6;
                    int pw = (nloc & 63) >> 1;
                    psm[ocl * 64 + pr * 32 + pw] = fmaxf(v0, v1);
                }
            }
        }
    }
    __syncthreads();

    int ph = n0 >> 7;
    for (int i = t; i < 64 * 32; i += 256) {
        int ocl = i >> 5, pw = i & 31;
        int oc = m0 + ocl;
        if (oc >= 32) {
            float v = fmaxf(psm[ocl * 64 + pw], psm[ocl * 64 + 32 + pw]);
            if (oc < 64)
                d_gbuf[((size_t)b * CK + oc - 32) * HWP + ph * 32 + pw] = f2tf(v + bg[oc - 32]);
            else
                d_hbuf[((size_t)b * CH + oc - 64) * HWP + ph * 32 + pw] = f2tf(v + bh[oc - 64]);
        }
    }
}

// ---------------------------------------------------------------------------
// Kernel 2: fused flash attention + output conv + residual.
// q-tile 128 per CTA, 512 threads (16 warps = 2 q-halves x old 8-warp layout).
// Mainloop: l-chunks of 64, f A-frags in regs, g/h double-buffered.
// Epilogue: O -> smem; out[256oc,128q] = gamma*(wv @ O^T + bv) + x,
// wv streamed in 8 double-buffered 32-oc chunks (2x amortization vs 64q CTA).
// ---------------------------------------------------------------------------
#define LC 64
#define NCHUNK 16
#define QT 128

__global__ __launch_bounds__(512, 1)
void attn_kernel(const float* __restrict__ x,
                 const float* __restrict__ bv,
                 const float* __restrict__ gamma_p,
                 float* __restrict__ out)
{
    extern __shared__ uint32_t sm[];
    uint32_t* g_s = sm;                         // 2 x [64 l][RS36]       4608 w
    uint32_t* h_s = g_s + 2 * 64 * RS36;        // 2 x [128 c][HP68]     17408 w
    uint32_t* p_u = h_s + 2 * 128 * HP68;       // [128 q][HP68]          8704 w
    float* row_part = reinterpret_cast<float*>(p_u + 128 * HP68);  // [4 wn][128]
    // epilogue overlays (reuse g/h region):
    uint32_t* o_s  = sm;                        // [128 q][PS]           16896 w
    uint32_t* wv_s = sm + 128 * PS;             // 2 x [32 oc][PS]        8448 w

    const int b  = blockIdx.y;
    const int q0 = blockIdx.x * QT;
    const int t = threadIdx.x, lane = t & 31, wid = t >> 5;
    const int wn = wid & 3;              // l/c split (0..3)
    const int wm = (wid >> 2) & 1;       // q 32-group
    const int wq = wid >> 3;             // q 64-half
    const int qb = wq * 64 + wm * 32;    // warp q base (0,32,64,96)

    const uint32_t* fb = d_f    + (size_t)b * CK * HW;
    const uint32_t* gb = d_gbuf + (size_t)b * CK * HWP;
    const uint32_t* hb = d_hbuf + (size_t)b * CH * HWP;

    auto issue_chunk = [&](int lc, int buf) {
        uint32_t* gd = g_s + buf * 64 * RS36;
        uint32_t* hd = h_s + buf * 128 * HP68;
        // g: [64 l][32 c] transposed gather, cp4 (512 (l,c4) pairs)
        {
            int l  = t & 63;
            int c4 = (t >> 6) * 4;
            #pragma unroll
            for (int j = 0; j < 4; j++)
                cp4(&gd[l * RS36 + c4 + j], gb + (size_t)(c4 + j) * HWP + lc + l);
        }
        // h: [128 c][64 l] native, cp16 (2048 transfers)
        #pragma unroll
        for (int ii = 0; ii < 4; ii++) {
            int i = t + ii * 512;                 // < 2048
            int c = i >> 4, l4 = (i & 15) * 4;
            cp16(&hd[c * HP68 + l4], hb + (size_t)c * HWP + lc + l4);
        }
        cp_commit();
    };

    issue_chunk(0, 0);

    // f A-fragments in registers (constant across chunks).
    uint32_t fa[2][4][4];
    {
        int r0 = q0 + qb + (lane >> 2);
        int c0 = lane & 3;
        #pragma unroll
        for (int mt = 0; mt < 2; mt++)
            #pragma unroll
            for (int kk = 0; kk < 4; kk++)
                #pragma unroll
                for (int j = 0; j < 4; j++) {
                    int row = r0 + mt * 16 + 8 * (j & 1);
                    int col = kk * 8 + c0 + 4 * (j >> 1);
                    fa[mt][kk][j] = fb[(size_t)col * HW + row];
                }
    }

    float acc[2][4][4] = {};
    float rsum[2][2] = {};

    for (int ic = 0; ic < NCHUNK; ic++) {
        cp_wait_all();
        __syncthreads();
        if (ic + 1 < NCHUNK) issue_chunk((ic + 1) * LC, (ic + 1) & 1);

        const uint32_t* gbuf = g_s + (ic & 1) * 64 * RS36;
        const uint32_t* hbuf = h_s + (ic & 1) * 128 * HP68;

        // --- S = f * g  (warp: 32q x 16l) ---
        float sacc[2][2][4] = {};
        #pragma unroll
        for (int kk = 0; kk < 4; kk++) {
            uint32_t bq[4];
            ldsmB(bq, gbuf, RS36, wn * 16, kk * 8, lane);
            mma8(sacc[0][0], fa[0][kk], bq); mma8(sacc[0][1], fa[0][kk], bq + 2);
            mma8(sacc[1][0], fa[1][kk], bq); mma8(sacc[1][1], fa[1][kk], bq + 2);
        }

        // --- exp on fragments, partial sums, store P (tf32) ---
        #pragma unroll
        for (int mt = 0; mt < 2; mt++) {
            int rb = qb + mt * 16 + (lane >> 2);
            #pragma unroll
            for (int nt = 0; nt < 2; nt++) {
                int cl = wn * 16 + nt * 8 + 2 * (lane & 3);
                float p0 = __expf(sacc[mt][nt][0]);
                float p1 = __expf(sacc[mt][nt][1]);
                float p2 = __expf(sacc[mt][nt][2]);
                float p3 = __expf(sacc[mt][nt][3]);
                rsum[mt][0] += p0 + p1;
                rsum[mt][1] += p2 + p3;
                *reinterpret_cast<uint2*>(&p_u[rb * HP68 + cl]) =
                    make_uint2(f2tf(p0), f2tf(p1));
                *reinterpret_cast<uint2*>(&p_u[(rb + 8) * HP68 + cl]) =
                    make_uint2(f2tf(p2), f2tf(p3));
            }
        }
        __syncthreads();

        // --- O += P * h^T  (warp: 32q x 32c, k = 64 l) ---
        #pragma unroll
        for (int kk = 0; kk < 8; kk++) {
            uint32_t a0[4], a1[4], b01[4], b23[4];
            ldsmA(a0, p_u, HP68, qb,      kk * 8, lane);
            ldsmA(a1, p_u, HP68, qb + 16, kk * 8, lane);
            ldsmB(b01, hbuf, HP68, wn * 32,      kk * 8, lane);
            ldsmB(b23, hbuf, HP68, wn * 32 + 16, kk * 8, lane);
            mma8(acc[0][0], a0, b01); mma8(acc[0][1], a0, b01 + 2);
            mma8(acc[0][2], a0, b23); mma8(acc[0][3], a0, b23 + 2);
            mma8(acc[1][0], a1, b01); mma8(acc[1][1], a1, b01 + 2);
            mma8(acc[1][2], a1, b23); mma8(acc[1][3], a1, b23 + 2);
        }
    }

    // final row-sum reduction (over lane&3, then across 4 wn warps)
    #pragma unroll
    for (int mt = 0; mt < 2; mt++)
        #pragma unroll
        for (int hh = 0; hh < 2; hh++) {
            float s = rsum[mt][hh];
            s += __shfl_xor_sync(0xffffffffu, s, 1);
            s += __shfl_xor_sync(0xffffffffu, s, 2);
            rsum[mt][hh] = s;
        }
    if ((lane & 3) == 0) {
        #pragma unroll
        for (int mt = 0; mt < 2; mt++)
            #pragma unroll
            for (int hh = 0; hh < 2; hh++) {
                int rb = qb + mt * 16 + hh * 8 + (lane >> 2);
                row_part[wn * QT + rb] = rsum[mt][hh];
            }
    }
    __syncthreads();   // row_part visible; all g/h/p reads done -> safe to overlay

    // --- issue first wv chunk, then normalize O into o_s[q][c] (tf32) ---
    auto issue_wv = [&](int mc, int buf) {
        uint32_t* ad = wv_s + buf * 32 * PS;
        #pragma unroll
        for (int ii = 0; ii < 2; ii++) {
            int i = t + ii * 512;               // < 1024
            int m = i >> 5, k4 = (i & 31) * 4;
            cp16(&ad[m * PS + k4], d_wvt + (size_t)(mc * 32 + m) * CH + k4);
        }
        cp_commit();
    };

    issue_wv(0, 0);

    #pragma unroll
    for (int mt = 0; mt < 2; mt++) {
        int rb = qb + mt * 16 + (lane >> 2);
        float d0 = row_part[rb]      + row_part[QT + rb]      + row_part[2 * QT + rb]      + row_part[3 * QT + rb];
        float d1 = row_part[rb + 8]  + row_part[QT + rb + 8]  + row_part[2 * QT + rb + 8]  + row_part[3 * QT + rb + 8];
        float inv0 = 1.f / d0;
        float inv1 = 1.f / d1;
        #pragma unroll
        for (int nt = 0; nt < 4; nt++) {
            int cc = wn * 32 + nt * 8 + 2 * (lane & 3);
            *reinterpret_cast<uint2*>(&o_s[rb * PS + cc]) =
                make_uint2(f2tf(acc[mt][nt][0] * inv0), f2tf(acc[mt][nt][1] * inv0));
            *reinterpret_cast<uint2*>(&o_s[(rb + 8) * PS + cc]) =
                make_uint2(f2tf(acc[mt][nt][2] * inv1), f2tf(acc[mt][nt][3] * inv1));
        }
    }

    // --- out[oc, q] = gamma * (wv @ O^T + bv) + x, 8 oc-chunks of 32 ---
    const float gamma = *gamma_p;
    const int wm2 = wid & 1;      // oc m16 select
    const int wq8 = wid >> 1;     // q n16 select (0..7)

    for (int mc = 0; mc < 8; mc++) {
        cp_wait_all();
        __syncthreads();   // wv chunk + (mc==0) o_s visible; prev reads done
        if (mc + 1 < 8) issue_wv(mc + 1, (mc + 1) & 1);

        const uint32_t* abuf = wv_s + (mc & 1) * 32 * PS;

        float oa[2][4] = {};
        #pragma unroll
        for (int kk = 0; kk < 16; kk++) {
            uint32_t a0[4], bq[4];
            ldsmA(a0, abuf, PS, wm2 * 16, kk * 8, lane);
            ldsmB(bq, o_s, PS, wq8 * 16, kk * 8, lane);
            mma8(oa[0], a0, bq); mma8(oa[1], a0, bq + 2);
        }

        #pragma unroll
        for (int dr = 0; dr < 2; dr++) {
            int oc = mc * 32 + wm2 * 16 + dr * 8 + (lane >> 2);
            float bias = bv[oc];
            size_t rowoff = ((size_t)b * C_IN + oc) * HW + q0;
            #pragma unroll
            for (int nt = 0; nt < 2; nt++) {
                int ql = wq8 * 16 + nt * 8 + 2 * (lane & 3);
                float2 xv = *reinterpret_cast<const float2*>(x + rowoff + ql);
                float2 v;
                v.x = gamma * (oa[nt][dr * 2 + 0] + bias) + xv.x;
                v.y = gamma * (oa[nt][dr * 2 + 1] + bias) + xv.y;
                *reinterpret_cast<float2*>(out + rowoff + ql) = v;
            }
        }
    }
}

// ---------------------------------------------------------------------------
extern "C" void kernel_launch(void* const* d_in, const int* in_sizes, int n_in,
                              void* d_out, int out_size)
{
    const float* x  = (const float*)d_in[0];
    const float* wf = (const float*)d_in[1];
    const float* bf = (const float*)d_in[2];
    const float* wg = (const float*)d_in[3];
    const float* bg = (const float*)d_in[4];
    const float* wh = (const float*)d_in[5];
    const float* bh = (const float*)d_in[6];
    const float* wv = (const float*)d_in[7];
    const float* bv = (const float*)d_in[8];
    const float* gamma = (const float*)d_in[9];
    float* out = (float*)d_out;

    const int proj_smem = (2 * 64 * RS36 + 2 * 128 * RS36) * (int)sizeof(uint32_t);
    const int attn_smem =
        (2 * 64 * RS36 + 2 * 128 * HP68 + 128 * HP68 + 4 * QT) * (int)sizeof(uint32_t);

    cudaFuncSetAttribute(proj_gemm, cudaFuncAttributeMaxDynamicSharedMemorySize, proj_smem);
    cudaFuncSetAttribute(attn_kernel, cudaFuncAttributeMaxDynamicSharedMemorySize, attn_smem);

    // 0) pre-convert weights to tf32
    int prep_total = OC_TOT * C_IN + C_IN * CH;
    prep_weights<<<(prep_total + 255) / 256, 256>>>(wf, wg, wh, wv);

    // 1) projections + fused pool
    dim3 g1(HW / 128, OC_TOT / 64, BATCH);
    proj_gemm<<<g1, 256, proj_smem>>>(x, bf, bg, bh);

    // 2) fused attention + output conv + residual (q-tile 128, 512 threads)
    dim3 g3(HW / QT, BATCH);
    attn_kernel<<<g3, 512, attn_smem>>>(x, bv, gamma, out);
}